// round 13
// baseline (speedup 1.0000x reference)
#include <cuda_runtime.h>

// Problem constants
#define N_SAMPLES 65536
#define EMB       1536
#define HALF      768        // e<HALF depends only on w (idx2); e>=HALF only on h (idx1)
#define BINS      257
#define PLANE     (BINS * BINS)
#define ROW_V8    192        // 32-byte chunks per 6KB row
#define HALF_V8   96

// Rows whose output lines are dirty-pinned in L2 via evict_last:
// 12288 rows * 6 KB = 75.5 MB (~60% of 126 MB L2).
#define PIN_ROWS 12288

// Builder: 13824 (e, p-chunk) warp-tasks, 3 per warp, single balanced wave.
#define PCHUNKS     9
#define BUILD_CTAS  576
#define BUILD_WARPS (BUILD_CTAS * 8)  // 4608; 13824 / 4608 == 3 exactly

// Factored 1D table: T[p][e] = pe_value(e,p) + lc[e]. 1.58 MB -> L2 resident.
__device__ __align__(128) float g_table[BINS * EMB];

// ---------------------------------------------------------------------------
// Kernel A (R11-proven, ~1.5us): balanced single-wave builder, MLP=3/thread.
// ---------------------------------------------------------------------------
__global__ void __launch_bounds__(256)
build_table_kernel(const float* __restrict__ pe, const float* __restrict__ lc) {
    const int w    = blockIdx.x * 8 + (threadIdx.x >> 5);
    const int lane = threadIdx.x & 31;

    int   ev[3], pv[3];
    float val[3], bias[3];

    #pragma unroll
    for (int t = 0; t < 3; t++) {
        const int task = w + t * BUILD_WARPS;
        const int e = task / PCHUNKS;
        const int k = task - e * PCHUNKS;
        const int p = k * 32 + lane;
        ev[t] = e; pv[t] = p;
        if (p < BINS) {
            const size_t off = (e < HALF) ? (size_t)p : (size_t)p * BINS;
            val[t]  = __ldg(&pe[(size_t)e * PLANE + off]);
            bias[t] = __ldg(&lc[e]);
        }
    }
    #pragma unroll
    for (int t = 0; t < 3; t++) {
        if (pv[t] < BINS)
            g_table[(size_t)pv[t] * EMB + ev[t]] = val[t] + bias[t];
    }
}

// ---------------------------------------------------------------------------
// Exact digitize (rel_err == 0.0 validated in R1-R11).
// ---------------------------------------------------------------------------
__device__ __forceinline__ int digitize256(float x) {
    float xc = fminf(fmaxf(x, -5.0f), 5.0f - 1e-6f);
    int k = (int)floorf((xc + 5.0f) * 25.6f);
    k = max(0, min(k, 255));
    while (k < 255 && fmaf((float)(k + 1), 0.0390625f, -5.0f) <= xc) k++;
    while (k > 0   && fmaf((float)k,       0.0390625f, -5.0f) >  xc) k--;
    return k + 1;
}

// -------- 256-bit vector ld/st (R6-proven on sm_103a) ------------------------
struct V8 { float v[8]; };

__device__ __forceinline__ V8 ldg256(const float* p) {
    V8 r;
    asm volatile("ld.global.nc.v8.f32 {%0,%1,%2,%3,%4,%5,%6,%7}, [%8];"
                 : "=f"(r.v[0]), "=f"(r.v[1]), "=f"(r.v[2]), "=f"(r.v[3]),
                   "=f"(r.v[4]), "=f"(r.v[5]), "=f"(r.v[6]), "=f"(r.v[7])
                 : "l"(p));
    return r;
}
// Dirty-pin store: line stays L2-resident across graph replays; its DRAM
// writeback is elided because the next replay overwrites it in place.
__device__ __forceinline__ void stg256_pin(float* p, const V8& r) {
    asm volatile("st.global.L2::evict_last.v8.f32 [%0], {%1,%2,%3,%4,%5,%6,%7,%8};"
                 :: "l"(p),
                    "f"(r.v[0]), "f"(r.v[1]), "f"(r.v[2]), "f"(r.v[3]),
                    "f"(r.v[4]), "f"(r.v[5]), "f"(r.v[6]), "f"(r.v[7])
                 : "memory");
}
// Streaming store (evict-first): drain straight toward DRAM.
__device__ __forceinline__ void stg256_cs(float* p, const V8& r) {
    asm volatile("st.global.cs.v8.f32 [%0], {%1,%2,%3,%4,%5,%6,%7,%8};"
                 :: "l"(p),
                    "f"(r.v[0]), "f"(r.v[1]), "f"(r.v[2]), "f"(r.v[3]),
                    "f"(r.v[4]), "f"(r.v[5]), "f"(r.v[6]), "f"(r.v[7])
                 : "memory");
}

// ---------------------------------------------------------------------------
// Kernel B: warp-per-row copy (R6-proven 256-bit variant, 63.5us) with split
// store policy: rows < PIN_ROWS use evict_last (L2 dirty-pin), rest use .cs.
// Chunk c in [0,192): c < 96 -> W half (idx2), else H half (idx1).
// ---------------------------------------------------------------------------
__global__ void __launch_bounds__(256)
row_copy_kernel(const float* __restrict__ x1,
                const float* __restrict__ x2,
                float* __restrict__ out) {
    const int warp = threadIdx.x >> 5;
    const int lane = threadIdx.x & 31;
    const int row0 = blockIdx.x * 32 + warp;

    #pragma unroll
    for (int r = 0; r < 4; r++) {
        const int row = row0 + r * 8;
        const int i1 = digitize256(__ldg(&x1[row]));
        const int i2 = digitize256(__ldg(&x2[row]));
        const float* __restrict__ srcW = g_table + (size_t)i2 * EMB; // e <  768
        const float* __restrict__ srcH = g_table + (size_t)i1 * EMB; // e >= 768
        float* __restrict__ dst = out + (size_t)row * EMB;

        if (row < PIN_ROWS) {
            #pragma unroll
            for (int k = 0; k < 6; k++) {
                const int c = k * 32 + lane;                  // 0..191
                const float* s = (c < HALF_V8) ? srcW : srcH;
                stg256_pin(dst + (size_t)c * 8, ldg256(s + (size_t)c * 8));
            }
        } else {
            #pragma unroll
            for (int k = 0; k < 6; k++) {
                const int c = k * 32 + lane;
                const float* s = (c < HALF_V8) ? srcW : srcH;
                stg256_cs(dst + (size_t)c * 8, ldg256(s + (size_t)c * 8));
            }
        }
    }
}

extern "C" void kernel_launch(void* const* d_in, const int* in_sizes, int n_in,
                              void* d_out, int out_size) {
    const float* x1 = (const float*)d_in[0];
    const float* x2 = (const float*)d_in[1];
    const float* pe = (const float*)d_in[2];
    const float* lc = (const float*)d_in[3];

    build_table_kernel<<<BUILD_CTAS, 256>>>(pe, lc);
    row_copy_kernel<<<N_SAMPLES / 32, 256>>>(x1, x2, (float*)d_out);
}

// round 15
// speedup vs baseline: 1.0039x; 1.0039x over previous
#include <cuda_runtime.h>

// Problem constants
#define N_SAMPLES 65536
#define EMB       1536
#define HALF      768        // e<HALF depends only on w (idx2); e>=HALF only on h (idx1)
#define BINS      257
#define PLANE     (BINS * BINS)
#define ROW_V8    192        // 32-byte chunks per 6KB row
#define HALF_V8   96

// Builder: 13824 (e, p-chunk) warp-tasks, 3 per warp, single balanced wave.
#define PCHUNKS     9
#define BUILD_CTAS  576
#define BUILD_WARPS (BUILD_CTAS * 8)  // 4608; 13824 / 4608 == 3 exactly

// Factored 1D table: T[p][e] = pe_value(e,p) + lc[e]. 1.58 MB -> L2 resident.
__device__ __align__(128) float g_table[BINS * EMB];

// ---------------------------------------------------------------------------
// Kernel A (R11-proven, ~1.5us): balanced single-wave builder, MLP=3/thread.
// ---------------------------------------------------------------------------
__global__ void __launch_bounds__(256)
build_table_kernel(const float* __restrict__ pe, const float* __restrict__ lc) {
    const int w    = blockIdx.x * 8 + (threadIdx.x >> 5);
    const int lane = threadIdx.x & 31;

    int   ev[3], pv[3];
    float val[3], bias[3];

    #pragma unroll
    for (int t = 0; t < 3; t++) {
        const int task = w + t * BUILD_WARPS;
        const int e = task / PCHUNKS;
        const int k = task - e * PCHUNKS;
        const int p = k * 32 + lane;
        ev[t] = e; pv[t] = p;
        if (p < BINS) {
            const size_t off = (e < HALF) ? (size_t)p : (size_t)p * BINS;
            val[t]  = __ldg(&pe[(size_t)e * PLANE + off]);
            bias[t] = __ldg(&lc[e]);
        }
    }
    #pragma unroll
    for (int t = 0; t < 3; t++) {
        if (pv[t] < BINS)
            g_table[(size_t)pv[t] * EMB + ev[t]] = val[t] + bias[t];
    }
}

// ---------------------------------------------------------------------------
// Exact digitize (rel_err == 0.0 validated in R1-R13).
// ---------------------------------------------------------------------------
__device__ __forceinline__ int digitize256(float x) {
    float xc = fminf(fmaxf(x, -5.0f), 5.0f - 1e-6f);
    int k = (int)floorf((xc + 5.0f) * 25.6f);
    k = max(0, min(k, 255));
    while (k < 255 && fmaf((float)(k + 1), 0.0390625f, -5.0f) <= xc) k++;
    while (k > 0   && fmaf((float)k,       0.0390625f, -5.0f) >  xc) k--;
    return k + 1;
}

// -------- 256-bit vector ld/st (R6/R13-proven on sm_103a) --------------------
struct V8 { float v[8]; };

// Table read: non-coherent + L2 evict_last (keep 1.58 MB table resident
// against the evict-first output write stream). Load hint only, no drain
// side effects. 256-bit width required by ptxas for this modifier.
__device__ __forceinline__ V8 ld_tab256(const float* p) {
    V8 r;
    asm volatile("ld.global.nc.L2::evict_last.v8.f32 {%0,%1,%2,%3,%4,%5,%6,%7}, [%8];"
                 : "=f"(r.v[0]), "=f"(r.v[1]), "=f"(r.v[2]), "=f"(r.v[3]),
                   "=f"(r.v[4]), "=f"(r.v[5]), "=f"(r.v[6]), "=f"(r.v[7])
                 : "l"(p));
    return r;
}
// Streaming store (evict-first): drain straight toward DRAM (R13-proven path).
__device__ __forceinline__ void stg256_cs(float* p, const V8& r) {
    asm volatile("st.global.cs.v8.f32 [%0], {%1,%2,%3,%4,%5,%6,%7,%8};"
                 :: "l"(p),
                    "f"(r.v[0]), "f"(r.v[1]), "f"(r.v[2]), "f"(r.v[3]),
                    "f"(r.v[4]), "f"(r.v[5]), "f"(r.v[6]), "f"(r.v[7])
                 : "memory");
}

// ---------------------------------------------------------------------------
// Kernel B: warp-per-row copy (R6-proven 256-bit variant): 6 LDG.256
// (evict_last table reads) + 6 STG.256 (.cs streaming) per row, 4 rows/warp.
// Chunk c in [0,192): c < 96 -> W half (idx2), else H half (idx1).
// ---------------------------------------------------------------------------
__global__ void __launch_bounds__(256)
row_copy_kernel(const float* __restrict__ x1,
                const float* __restrict__ x2,
                float* __restrict__ out) {
    const int warp = threadIdx.x >> 5;
    const int lane = threadIdx.x & 31;
    const int row0 = blockIdx.x * 32 + warp;

    #pragma unroll
    for (int r = 0; r < 4; r++) {
        const int row = row0 + r * 8;
        const int i1 = digitize256(__ldg(&x1[row]));
        const int i2 = digitize256(__ldg(&x2[row]));
        const float* __restrict__ srcW = g_table + (size_t)i2 * EMB; // e <  768
        const float* __restrict__ srcH = g_table + (size_t)i1 * EMB; // e >= 768
        float* __restrict__ dst = out + (size_t)row * EMB;

        #pragma unroll
        for (int k = 0; k < 6; k++) {
            const int c = k * 32 + lane;                  // 0..191
            const float* s = (c < HALF_V8) ? srcW : srcH;
            stg256_cs(dst + (size_t)c * 8, ld_tab256(s + (size_t)c * 8));
        }
    }
}

extern "C" void kernel_launch(void* const* d_in, const int* in_sizes, int n_in,
                              void* d_out, int out_size) {
    const float* x1 = (const float*)d_in[0];
    const float* x2 = (const float*)d_in[1];
    const float* pe = (const float*)d_in[2];
    const float* lc = (const float*)d_in[3];

    build_table_kernel<<<BUILD_CTAS, 256>>>(pe, lc);
    row_copy_kernel<<<N_SAMPLES / 32, 256>>>(x1, x2, (float*)d_out);
}